// round 1
// baseline (speedup 1.0000x reference)
#include <cuda_runtime.h>

#define BATCH  2048
#define LATENT 64
#define NJ     64           // number of j-chunks
#define JC     (BATCH/NJ)   // 32 j per chunk
#define IB     128          // i per CTA

static __constant__ const float c_dummy = 0.0f; // keep nvcc happy about empty constant use

#define LOG2E_F   1.4426950408889634f
#define LN2_F     0.6931471805599453f
#define LOG2PI_F  1.8378770664093453f
#define BETA_F    6.0f

// ---- device scratch (static; no allocation anywhere) ----
__device__ float d_A [BATCH*LATENT];      // log2-domain quadratic coeff
__device__ float d_Bc[BATCH*LATENT];      // log2-domain linear coeff
__device__ float d_G [BATCH*LATENT];      // log2-domain constant coeff
__device__ float d_kl[BATCH];             // per-sample KL (0.5 * sum_l ...)
__device__ float d_accP[NJ*LATENT*BATCH]; // per-(chunk,l,i) partial sum of exp  (32MB)
__device__ float d_m2P [NJ*BATCH];        // per-(chunk,i) running max (log2 domain)
__device__ float d_t2P [NJ*BATCH];        // per-(chunk,i) running scaled sum
__device__ float d_lqp [LATENT*BATCH];    // per-(l,i) log2(sum_j exp(p))
__device__ float d_val [BATCH];           // per-i final value

// ---- tiny PTX helpers ----
__device__ __forceinline__ float ex2f(float x){ float r; asm("ex2.approx.f32 %0, %1;" : "=f"(r) : "f"(x)); return r; }
__device__ __forceinline__ float lg2f(float x){ float r; asm("lg2.approx.f32 %0, %1;" : "=f"(r) : "f"(x)); return r; }
typedef unsigned long long u64;
__device__ __forceinline__ u64 fma2(u64 a, u64 b, u64 c){ u64 d; asm("fma.rn.f32x2 %0, %1, %2, %3;" : "=l"(d) : "l"(a), "l"(b), "l"(c)); return d; }
__device__ __forceinline__ u64 add2(u64 a, u64 b){ u64 d; asm("add.rn.f32x2 %0, %1, %2;" : "=l"(d) : "l"(a), "l"(b)); return d; }
__device__ __forceinline__ void upk(u64 v, float& lo, float& hi){ asm("mov.b64 {%0, %1}, %2;" : "=f"(lo), "=f"(hi) : "l"(v)); }

// ---- kernel 0: precompute coefficients + per-sample KL ----
// p_natural(i,j,l) = a*(z-m)^2 + c  with a = -0.5*exp(-lv), c = -0.5*(lv + LOG2PI)
// expanded & converted to log2 domain:
//   p2 = A*z^2 + B*z + G,  A = a*log2e, B = exp(-lv)*m*log2e, G = (a*m^2 + c)*log2e
__global__ void btc_prep(const float* __restrict__ zmean, const float* __restrict__ zlogvar)
{
    int j = blockIdx.x * blockDim.x + threadIdx.x;
    if (j >= BATCH) return;
    float kl = 0.f;
    #pragma unroll 8
    for (int l = 0; l < LATENT; l++) {
        float m  = zmean[j*LATENT + l];
        float lv = zlogvar[j*LATENT + l];
        float invs = ex2f(-lv * LOG2E_F);     // exp(-lv)
        float elv  = ex2f( lv * LOG2E_F);     // exp(lv)
        kl += m*m + elv - lv - 1.f;
        float a = -0.5f * invs;
        d_A [j*LATENT + l] = a * LOG2E_F;
        d_Bc[j*LATENT + l] = invs * m * LOG2E_F;
        d_G [j*LATENT + l] = (a*m*m - 0.5f*(lv + LOG2PI_F)) * LOG2E_F;
    }
    d_kl[j] = 0.5f * kl;
}

// ---- kernel 1: the 268M-element main pass ----
// thread = one i; CTA = 128 i's x one j-chunk of 32.
// acc[l]  = sum_j exp(p)      (64 fp32 registers)
// (M, T)  = online logsumexp over j of S_ij = sum_l p2  (log2 domain)
__global__ void __launch_bounds__(IB) btc_main(const float* __restrict__ z)
{
    __shared__ u64 sA[JC*LATENT/2];
    __shared__ u64 sB[JC*LATENT/2];
    __shared__ u64 sG[JC*LATENT/2];

    const int i     = blockIdx.x * IB + threadIdx.x;
    const int ch    = blockIdx.y;
    const int jbase = ch * JC;

    // stage coefficients for this j-chunk (JC*LATENT = 2048 floats each)
    {
        const float4* gA = (const float4*)(d_A  + jbase*LATENT);
        const float4* gB = (const float4*)(d_Bc + jbase*LATENT);
        const float4* gG = (const float4*)(d_G  + jbase*LATENT);
        for (int t = threadIdx.x; t < JC*LATENT/4; t += IB) {
            ((float4*)sA)[t] = gA[t];
            ((float4*)sB)[t] = gB[t];
            ((float4*)sG)[t] = gG[t];
        }
    }
    __syncthreads();

    // z row in registers, packed f32x2
    u64 zr[LATENT/2];
    const u64* zp = (const u64*)(z + i*LATENT);
    #pragma unroll
    for (int p = 0; p < LATENT/2; p++) zr[p] = zp[p];

    float acc[LATENT];
    #pragma unroll
    for (int l = 0; l < LATENT; l++) acc[l] = 0.f;

    float M = -1e30f, T = 0.f;

    for (int jl = 0; jl < JC; jl++) {
        u64 s2 = 0ull; // packed (0.f, 0.f)
        #pragma unroll
        for (int p = 0; p < LATENT/2; p++) {
            u64 A  = sA[jl*(LATENT/2) + p];
            u64 B  = sB[jl*(LATENT/2) + p];
            u64 G  = sG[jl*(LATENT/2) + p];
            u64 t1 = fma2(A, zr[p], B);
            u64 pp = fma2(t1, zr[p], G);     // log2-domain log-prob (2 lanes of l)
            float p0, p1; upk(pp, p0, p1);
            acc[2*p  ] += ex2f(p0);
            acc[2*p+1] += ex2f(p1);
            s2 = add2(s2, pp);
        }
        float s0, s1; upk(s2, s0, s1);
        float S  = s0 + s1;                  // S_ij in log2 domain
        float nM = fmaxf(M, S);
        T = T * ex2f(M - nM) + ex2f(S - nM); // branchless online LSE
        M = nM;
    }

    // write partials (coalesced over i)
    #pragma unroll
    for (int l = 0; l < LATENT; l++)
        d_accP[(ch*LATENT + l)*BATCH + i] = acc[l];
    d_m2P[ch*BATCH + i] = M;
    d_t2P[ch*BATCH + i] = T;
}

// ---- kernel 2a: sum exp-partials over chunks, take log2  (parallel over (i,l)) ----
__global__ void btc_k2a()
{
    int idx = blockIdx.x * blockDim.x + threadIdx.x;   // 131072 threads
    int l = idx >> 11;
    int i = idx & (BATCH - 1);
    float tot = 0.f;
    #pragma unroll 8
    for (int ch = 0; ch < NJ; ch++)
        tot += d_accP[(ch*LATENT + l)*BATCH + i];
    d_lqp[l*BATCH + i] = lg2f(tot);
}

// ---- kernel 2b: per-i combine ----
__global__ void btc_k2b()
{
    int i = blockIdx.x * blockDim.x + threadIdx.x;     // 2048 threads
    float lqp2 = 0.f;
    #pragma unroll 8
    for (int l = 0; l < LATENT; l++) lqp2 += d_lqp[l*BATCH + i];

    float M = -1e30f, T = 0.f;
    #pragma unroll 8
    for (int ch = 0; ch < NJ; ch++) {
        float m = d_m2P[ch*BATCH + i];
        float t = d_t2P[ch*BATCH + i];
        float nM = fmaxf(M, m);
        T = T * ex2f(M - nM) + t * ex2f(m - nM);
        M = nM;
    }
    float lq2 = M + lg2f(T);
    d_val[i] = (BETA_F - 1.f) * LN2_F * (lq2 - lqp2) + d_kl[i];
}

// ---- kernel 3: deterministic final mean ----
__global__ void btc_final(float* __restrict__ out)
{
    __shared__ float sh[256];
    float s = 0.f;
    for (int k = threadIdx.x; k < BATCH; k += 256) s += d_val[k];
    sh[threadIdx.x] = s;
    __syncthreads();
    for (int st = 128; st > 0; st >>= 1) {
        if (threadIdx.x < st) sh[threadIdx.x] += sh[threadIdx.x + st];
        __syncthreads();
    }
    if (threadIdx.x == 0) out[0] = sh[0] / (float)BATCH;
}

extern "C" void kernel_launch(void* const* d_in, const int* in_sizes, int n_in,
                              void* d_out, int out_size)
{
    const float* z  = (const float*)d_in[0];
    const float* zm = (const float*)d_in[1];
    const float* zl = (const float*)d_in[2];
    (void)in_sizes; (void)n_in; (void)out_size; (void)c_dummy;

    btc_prep<<<BATCH/256, 256>>>(zm, zl);
    btc_main<<<dim3(BATCH/IB, NJ), IB>>>(z);
    btc_k2a<<<(BATCH*LATENT)/256, 256>>>();
    btc_k2b<<<BATCH/256, 256>>>();
    btc_final<<<1, 256>>>((float*)d_out);
}

// round 2
// speedup vs baseline: 1.0201x; 1.0201x over previous
#include <cuda_runtime.h>
#include <cuda_fp16.h>

#define BATCH  2048
#define LATENT 64
#define NJ     64           // number of j-chunks
#define JC     (BATCH/NJ)   // 32 j per chunk
#define IB     128          // i per CTA
#define NP     (LATENT/2)   // 32 pairs

#define LOG2E_F   1.4426950408889634f
#define LN2_F     0.6931471805599453f
#define LOG2PI_F  1.8378770664093453f
#define BETA_F    6.0f

// ---- device scratch (static; no allocation anywhere) ----
__device__ float d_AB [BATCH*NP*4];        // interleaved {A0,A1,B0,B1} per (j,pair)  (2MB)
__device__ float d_G  [BATCH*LATENT];      // log2-domain constant coeff              (0.5MB)
__device__ float d_kl [BATCH];             // per-sample KL
__device__ unsigned int d_accP[NJ*NP*BATCH]; // per-(chunk,pair,i) half2 partial sums (16MB)
__device__ float d_m2P[NJ*BATCH];          // per-(chunk,i) running max (log2 domain)
__device__ float d_t2P[NJ*BATCH];          // per-(chunk,i) running scaled sum
__device__ float d_val[BATCH];             // per-i final value

// ---- tiny PTX helpers ----
__device__ __forceinline__ float ex2f(float x){ float r; asm("ex2.approx.f32 %0, %1;" : "=f"(r) : "f"(x)); return r; }
__device__ __forceinline__ float lg2f(float x){ float r; asm("lg2.approx.f32 %0, %1;" : "=f"(r) : "f"(x)); return r; }
typedef unsigned long long u64;
__device__ __forceinline__ u64 fma2(u64 a, u64 b, u64 c){ u64 d; asm("fma.rn.f32x2 %0, %1, %2, %3;" : "=l"(d) : "l"(a), "l"(b), "l"(c)); return d; }
__device__ __forceinline__ u64 add2(u64 a, u64 b){ u64 d; asm("add.rn.f32x2 %0, %1, %2;" : "=l"(d) : "l"(a), "l"(b)); return d; }
__device__ __forceinline__ void upk(u64 v, float& lo, float& hi){ asm("mov.b64 {%0, %1}, %2;" : "=f"(lo), "=f"(hi) : "l"(v)); }
__device__ __forceinline__ u64 pk2(unsigned lo, unsigned hi){ u64 r; asm("mov.b64 %0, {%1, %2};" : "=l"(r) : "r"(lo), "r"(hi)); return r; }
// pack two f32 -> f16x2  (lo half = a, hi half = b)
__device__ __forceinline__ unsigned cvt_h2(float a, float b){ unsigned r; asm("cvt.rn.f16x2.f32 %0, %1, %2;" : "=r"(r) : "f"(b), "f"(a)); return r; }
__device__ __forceinline__ unsigned hex2(unsigned x){ unsigned r; asm("ex2.approx.f16x2 %0, %1;" : "=r"(r) : "r"(x)); return r; }
__device__ __forceinline__ unsigned hadd2(unsigned a, unsigned b){ unsigned r; asm("add.rn.f16x2 %0, %1, %2;" : "=r"(r) : "r"(a), "r"(b)); return r; }

// ---- kernel 0: precompute coefficients + per-sample KL ----
// p2(i,j,l) = A*z^2 + B*z + G  (log2 domain)
__global__ void btc_prep(const float* __restrict__ zmean, const float* __restrict__ zlogvar)
{
    int j = blockIdx.x * blockDim.x + threadIdx.x;
    if (j >= BATCH) return;
    float kl = 0.f;
    #pragma unroll 8
    for (int l = 0; l < LATENT; l++) {
        float m  = zmean[j*LATENT + l];
        float lv = zlogvar[j*LATENT + l];
        float invs = ex2f(-lv * LOG2E_F);     // exp(-lv)
        float elv  = ex2f( lv * LOG2E_F);     // exp(lv)
        kl += m*m + elv - lv - 1.f;
        float a = -0.5f * invs;
        int p = l >> 1, h = l & 1;
        d_AB[(j*NP + p)*4 + h    ] = a * LOG2E_F;                      // A
        d_AB[(j*NP + p)*4 + 2 + h] = invs * m * LOG2E_F;               // B
        d_G [j*LATENT + l]         = (a*m*m - 0.5f*(lv + LOG2PI_F)) * LOG2E_F;
    }
    d_kl[j] = 0.5f * kl;
}

// ---- kernel 1: the 268M-element main pass (fp16x2 exp path) ----
__global__ void __launch_bounds__(IB) btc_main(const float* __restrict__ z)
{
    __shared__ uint4 sAB[JC*NP];   // 16KB: {A-pair(u64), B-pair(u64)} per (j,pair)
    __shared__ u64   sG [JC*NP];   // 8KB

    const int i     = blockIdx.x * IB + threadIdx.x;
    const int ch    = blockIdx.y;
    const int jbase = ch * JC;

    // stage coefficients for this j-chunk
    {
        const float4* gAB = (const float4*)(d_AB + jbase*NP*4);
        const float4* gG  = (const float4*)(d_G  + jbase*LATENT);
        for (int t = threadIdx.x; t < JC*NP; t += IB)
            sAB[t] = ((const uint4*)gAB)[t];
        for (int t = threadIdx.x; t < JC*NP/2; t += IB)
            ((float4*)sG)[t] = gG[t];
    }
    __syncthreads();

    // z row in registers, packed f32x2
    u64 zr[NP];
    const u64* zp = (const u64*)(z + i*LATENT);
    #pragma unroll
    for (int p = 0; p < NP; p++) zr[p] = zp[p];

    unsigned hacc[NP];             // half2 accumulators (sum over the 32 j in this chunk)
    #pragma unroll
    for (int p = 0; p < NP; p++) hacc[p] = 0u;

    float M = -1e30f, T = 0.f;

    for (int jl = 0; jl < JC; jl++) {
        u64 s2 = 0ull;
        #pragma unroll
        for (int p = 0; p < NP; p++) {
            uint4 q = sAB[jl*NP + p];
            u64 A   = pk2(q.x, q.y);
            u64 B   = pk2(q.z, q.w);
            u64 G   = sG[jl*NP + p];
            u64 t1  = fma2(A, zr[p], B);
            u64 pp  = fma2(t1, zr[p], G);     // log2-domain log-prob (2 lanes of l)
            s2 = add2(s2, pp);
            float p0, p1; upk(pp, p0, p1);
            hacc[p] = hadd2(hacc[p], hex2(cvt_h2(p0, p1)));
        }
        float s0, s1; upk(s2, s0, s1);
        float S  = s0 + s1;                  // S_ij in log2 domain
        float nM = fmaxf(M, S);
        T = T * ex2f(M - nM) + ex2f(S - nM); // branchless online LSE
        M = nM;
    }

    // write partials (coalesced over i)
    #pragma unroll
    for (int p = 0; p < NP; p++)
        d_accP[(ch*NP + p)*BATCH + i] = hacc[p];
    d_m2P[ch*BATCH + i] = M;
    d_t2P[ch*BATCH + i] = T;
}

// ---- kernel 2: fused reduction. CTA = 32 i's, 8-way parallel per i ----
__global__ void __launch_bounds__(256) btc_k2()
{
    __shared__ float s_lqp[8][32];
    __shared__ float s_m  [8][32];
    __shared__ float s_t  [8][32];

    const int li = threadIdx.x & 31;       // i within block
    const int g  = threadIdx.x >> 5;       // group 0..7
    const int i  = blockIdx.x * 32 + li;

    // Phase A: per-dim sums across chunks -> log2, for 4 pairs per group
    float lqp = 0.f;
    #pragma unroll
    for (int pp = 0; pp < 4; pp++) {
        const int p = g*4 + pp;
        float s0 = 0.f, s1 = 0.f;
        #pragma unroll 8
        for (int ch = 0; ch < NJ; ch++) {
            __half2 h = *reinterpret_cast<const __half2*>(&d_accP[(ch*NP + p)*BATCH + i]);
            float2 f = __half22float2(h);
            s0 += f.x; s1 += f.y;
        }
        lqp += lg2f(s0) + lg2f(s1);
    }
    s_lqp[g][li] = lqp;

    // Phase B: chunk-LSE combine, 8 chunks per group
    float M = -1e30f, T = 0.f;
    #pragma unroll
    for (int cc = 0; cc < 8; cc++) {
        const int ch = g*8 + cc;
        float m = d_m2P[ch*BATCH + i];
        float t = d_t2P[ch*BATCH + i];
        float nM = fmaxf(M, m);
        T = T * ex2f(M - nM) + t * ex2f(m - nM);
        M = nM;
    }
    s_m[g][li] = M;
    s_t[g][li] = T;
    __syncthreads();

    if (g == 0) {
        float lqp_tot = 0.f;
        float Mf = -1e30f, Tf = 0.f;
        #pragma unroll
        for (int gg = 0; gg < 8; gg++) {
            lqp_tot += s_lqp[gg][li];
            float m = s_m[gg][li], t = s_t[gg][li];
            float nM = fmaxf(Mf, m);
            Tf = Tf * ex2f(Mf - nM) + t * ex2f(m - nM);
            Mf = nM;
        }
        float lq2 = Mf + lg2f(Tf);
        d_val[i] = (BETA_F - 1.f) * LN2_F * (lq2 - lqp_tot) + d_kl[i];
    }
}

// ---- kernel 3: deterministic final mean ----
__global__ void btc_final(float* __restrict__ out)
{
    __shared__ float sh[256];
    float s = 0.f;
    for (int k = threadIdx.x; k < BATCH; k += 256) s += d_val[k];
    sh[threadIdx.x] = s;
    __syncthreads();
    for (int st = 128; st > 0; st >>= 1) {
        if (threadIdx.x < st) sh[threadIdx.x] += sh[threadIdx.x + st];
        __syncthreads();
    }
    if (threadIdx.x == 0) out[0] = sh[0] / (float)BATCH;
}

extern "C" void kernel_launch(void* const* d_in, const int* in_sizes, int n_in,
                              void* d_out, int out_size)
{
    const float* z  = (const float*)d_in[0];
    const float* zm = (const float*)d_in[1];
    const float* zl = (const float*)d_in[2];
    (void)in_sizes; (void)n_in; (void)out_size;

    btc_prep<<<BATCH/256, 256>>>(zm, zl);
    btc_main<<<dim3(BATCH/IB, NJ), IB>>>(z);
    btc_k2<<<BATCH/32, 256>>>();
    btc_final<<<1, 256>>>((float*)d_out);
}

// round 3
// speedup vs baseline: 1.8053x; 1.7697x over previous
#include <cuda_runtime.h>
#include <cuda_fp16.h>

#define BATCH  2048
#define LATENT 64
#define NJ     64           // number of j-chunks
#define JC     (BATCH/NJ)   // 32 j per chunk
#define IB     128          // i per CTA
#define NP     (LATENT/2)   // 32 pairs

#define LOG2E_F   1.4426950408889634f
#define LN2_F     0.6931471805599453f
#define LOG2PI_F  1.8378770664093453f

// ---- device scratch (static; no allocation anywhere) ----
__device__ unsigned int d_accP[NJ*NP*BATCH]; // per-(chunk,pair,i) half2 partial sums (16MB)
__device__ float d_m2P[NJ*BATCH];            // per-(chunk,i) running max (log2 domain)
__device__ float d_t2P[NJ*BATCH];            // per-(chunk,i) running scaled sum
__device__ float d_val[BATCH];               // per-i final value
__device__ unsigned int d_ctr;               // last-block counter

// ---- tiny PTX helpers ----
__device__ __forceinline__ float ex2f(float x){ float r; asm("ex2.approx.f32 %0, %1;" : "=f"(r) : "f"(x)); return r; }
__device__ __forceinline__ float lg2f(float x){ float r; asm("lg2.approx.f32 %0, %1;" : "=f"(r) : "f"(x)); return r; }
typedef unsigned long long u64;
__device__ __forceinline__ u64 fma2(u64 a, u64 b, u64 c){ u64 d; asm("fma.rn.f32x2 %0, %1, %2, %3;" : "=l"(d) : "l"(a), "l"(b), "l"(c)); return d; }
__device__ __forceinline__ u64 add2(u64 a, u64 b){ u64 d; asm("add.rn.f32x2 %0, %1, %2;" : "=l"(d) : "l"(a), "l"(b)); return d; }
__device__ __forceinline__ void upk(u64 v, float& lo, float& hi){ asm("mov.b64 {%0, %1}, %2;" : "=f"(lo), "=f"(hi) : "l"(v)); }
__device__ __forceinline__ u64 pkf2(float lo, float hi){ u64 r; asm("mov.b64 %0, {%1, %2};" : "=l"(r) : "f"(lo), "f"(hi)); return r; }
__device__ __forceinline__ unsigned cvt_h2(float a, float b){ unsigned r; asm("cvt.rn.f16x2.f32 %0, %1, %2;" : "=r"(r) : "f"(b), "f"(a)); return r; }
__device__ __forceinline__ unsigned hex2(unsigned x){ unsigned r; asm("ex2.approx.f16x2 %0, %1;" : "=r"(r) : "r"(x)); return r; }
__device__ __forceinline__ unsigned hadd2(unsigned a, unsigned b){ unsigned r; asm("add.rn.f16x2 %0, %1, %2;" : "=r"(r) : "r"(a), "r"(b)); return r; }

// ==== kernel 1: main pass (coefficient prep inlined, 268M exps) ====
// CTA = 128 i's  x  one 32-j chunk.
// smem coeff record per (j,pair): {A01 (u64), B01 (u64)} at sAB, G01 (u64) at sG.
__global__ void __launch_bounds__(IB) btc_main(const float* __restrict__ z,
                                               const float* __restrict__ zm,
                                               const float* __restrict__ zl)
{
    __shared__ float sAB[JC*NP*4];   // 16KB, 16B record per (j,p): A0 A1 B0 B1
    __shared__ float sG [JC*NP*2];   // 8KB

    const int ch    = blockIdx.y;
    const int jbase = ch * JC;
    const int i     = blockIdx.x * IB + threadIdx.x;

    if (blockIdx.x == 0 && blockIdx.y == 0 && threadIdx.x == 0) d_ctr = 0;

    // ---- inline coefficient prep for this chunk's 32 j x 64 l ----
    #pragma unroll
    for (int k = 0; k < (JC*LATENT)/IB; k++) {
        int idx = threadIdx.x + k*IB;          // 0..2047, coalesced LDG
        int j = idx >> 6, l = idx & 63;
        float m  = zm[(jbase + j)*LATENT + l];
        float lv = zl[(jbase + j)*LATENT + l];
        float invs = ex2f(-lv * LOG2E_F);      // exp(-lv)
        float a = -0.5f * invs;
        int p = l >> 1, h = l & 1;
        sAB[(j*NP + p)*4 + h    ] = a * LOG2E_F;
        sAB[(j*NP + p)*4 + 2 + h] = invs * m * LOG2E_F;
        sG [(j*NP + p)*2 + h    ] = (a*m*m - 0.5f*(lv + LOG2PI_F)) * LOG2E_F;
    }
    __syncthreads();

    // ---- z row in registers, packed f32x2 ----
    u64 zr[NP];
    const float4* zp4 = (const float4*)(z + i*LATENT);
    #pragma unroll
    for (int q = 0; q < LATENT/4; q++) {
        float4 v = zp4[q];
        zr[2*q  ] = pkf2(v.x, v.y);
        zr[2*q+1] = pkf2(v.z, v.w);
    }

    unsigned hacc[NP];
    #pragma unroll
    for (int p = 0; p < NP; p++) hacc[p] = 0u;

    float M = -1e30f, T = 0.f;

    for (int jl = 0; jl < JC; jl++) {
        const ulonglong2* ab = (const ulonglong2*)&sAB[jl*NP*4];
        const u64*        gg = (const u64*)       &sG [jl*NP*2];
        u64 s2 = 0ull;
        #pragma unroll
        for (int p = 0; p < NP; p++) {
            ulonglong2 q = ab[p];                 // one LDS.128: {A01, B01}
            u64 t1 = fma2(q.x, zr[p], q.y);
            u64 pp = fma2(t1, zr[p], gg[p]);      // log2-domain log-prob (2 l's)
            s2 = add2(s2, pp);
            float p0, p1; upk(pp, p0, p1);
            hacc[p] = hadd2(hacc[p], hex2(cvt_h2(p0, p1)));
        }
        float s0, s1; upk(s2, s0, s1);
        float S  = s0 + s1;                       // S_ij in log2 domain
        float nM = fmaxf(M, S);
        T = T * ex2f(M - nM) + ex2f(S - nM);      // branchless online LSE
        M = nM;
    }

    // write partials (coalesced over i)
    #pragma unroll
    for (int p = 0; p < NP; p++)
        d_accP[(ch*NP + p)*BATCH + i] = hacc[p];
    d_m2P[ch*BATCH + i] = M;
    d_t2P[ch*BATCH + i] = T;
}

// ==== kernel 2: fused reduce + KL + final mean (last-block pattern) ====
__global__ void __launch_bounds__(256) btc_reduce(const float* __restrict__ zm,
                                                  const float* __restrict__ zl,
                                                  float* __restrict__ out)
{
    __shared__ float s_lqp[8][32];
    __shared__ float s_m  [8][32];
    __shared__ float s_t  [8][32];
    __shared__ float s_kl [8][32];
    __shared__ float sh[256];
    __shared__ unsigned s_done;

    const int li = threadIdx.x & 31;       // i within block
    const int g  = threadIdx.x >> 5;       // group 0..7
    const int i  = blockIdx.x * 32 + li;

    // Phase A: per-dim sums across chunks -> log2, plus KL terms (4 pairs per group)
    float lqp = 0.f, kl = 0.f;
    #pragma unroll
    for (int pp = 0; pp < 4; pp++) {
        const int p = g*4 + pp;
        float s0 = 0.f, s1 = 0.f;
        #pragma unroll 8
        for (int chn = 0; chn < NJ; chn++) {
            __half2 h = *reinterpret_cast<const __half2*>(&d_accP[(chn*NP + p)*BATCH + i]);
            float2 f = __half22float2(h);
            s0 += f.x; s1 += f.y;
        }
        lqp += lg2f(s0) + lg2f(s1);
        #pragma unroll
        for (int h = 0; h < 2; h++) {
            int l = 2*p + h;
            float m  = zm[i*LATENT + l];
            float lv = zl[i*LATENT + l];
            kl += m*m + ex2f(lv * LOG2E_F) - lv - 1.f;
        }
    }
    s_lqp[g][li] = lqp;
    s_kl [g][li] = kl;

    // Phase B: chunk-LSE combine, 8 chunks per group
    float M = -1e30f, T = 0.f;
    #pragma unroll
    for (int cc = 0; cc < 8; cc++) {
        const int chn = g*8 + cc;
        float m = d_m2P[chn*BATCH + i];
        float t = d_t2P[chn*BATCH + i];
        float nM = fmaxf(M, m);
        T = T * ex2f(M - nM) + t * ex2f(m - nM);
        M = nM;
    }
    s_m[g][li] = M;
    s_t[g][li] = T;
    __syncthreads();

    if (g == 0) {
        float lqp_tot = 0.f, kl_tot = 0.f;
        float Mf = -1e30f, Tf = 0.f;
        #pragma unroll
        for (int gg = 0; gg < 8; gg++) {
            lqp_tot += s_lqp[gg][li];
            kl_tot  += s_kl [gg][li];
            float m = s_m[gg][li], t = s_t[gg][li];
            float nM = fmaxf(Mf, m);
            Tf = Tf * ex2f(Mf - nM) + t * ex2f(m - nM);
            Mf = nM;
        }
        float lq2 = Mf + lg2f(Tf);
        d_val[i] = 5.0f * LN2_F * (lq2 - lqp_tot) + 0.5f * kl_tot;
    }
    __syncthreads();

    // last CTA to finish computes the deterministic mean
    __threadfence();
    if (threadIdx.x == 0) s_done = atomicAdd(&d_ctr, 1);
    __syncthreads();
    if (s_done == (BATCH/32) - 1) {
        __threadfence();
        float s = 0.f;
        for (int k = threadIdx.x; k < BATCH; k += 256) s += d_val[k];
        sh[threadIdx.x] = s;
        __syncthreads();
        for (int st = 128; st > 0; st >>= 1) {
            if (threadIdx.x < st) sh[threadIdx.x] += sh[threadIdx.x + st];
            __syncthreads();
        }
        if (threadIdx.x == 0) out[0] = sh[0] / (float)BATCH;
    }
}

extern "C" void kernel_launch(void* const* d_in, const int* in_sizes, int n_in,
                              void* d_out, int out_size)
{
    const float* z  = (const float*)d_in[0];
    const float* zm = (const float*)d_in[1];
    const float* zl = (const float*)d_in[2];
    (void)in_sizes; (void)n_in; (void)out_size;

    btc_main<<<dim3(BATCH/IB, NJ), IB>>>(z, zm, zl);
    btc_reduce<<<BATCH/32, 256>>>(zm, zl, (float*)d_out);
}

// round 4
// speedup vs baseline: 2.0348x; 1.1271x over previous
#include <cuda_runtime.h>
#include <cuda_fp16.h>

#define BATCH  2048
#define LATENT 64
#define NJ     64           // number of j-chunks
#define JC     (BATCH/NJ)   // 32 j per chunk
#define IB     128          // i per CTA
#define NP     (LATENT/2)   // 32 pairs
#define NQ     (LATENT/4)   // 16 quad-records

#define LOG2E_F   1.4426950408889634f
#define LN2_F     0.6931471805599453f
#define LOG2PI_F  1.8378770664093453f

// ---- device scratch (static; no allocation anywhere) ----
__device__ unsigned int d_accP[NJ*NP*BATCH]; // per-(chunk,pair,i) half2 partial sums (16MB)
__device__ float d_m2P[NJ*BATCH];            // per-(chunk,i) running max (log2 domain)
__device__ float d_t2P[NJ*BATCH];            // per-(chunk,i) running scaled sum
__device__ float d_val[BATCH];               // per-i final value
__device__ unsigned int d_ctr;               // last-block counter

// ---- tiny PTX helpers ----
__device__ __forceinline__ float ex2f(float x){ float r; asm("ex2.approx.f32 %0, %1;" : "=f"(r) : "f"(x)); return r; }
__device__ __forceinline__ float lg2f(float x){ float r; asm("lg2.approx.f32 %0, %1;" : "=f"(r) : "f"(x)); return r; }
typedef unsigned long long u64;
__device__ __forceinline__ u64 fma2(u64 a, u64 b, u64 c){ u64 d; asm("fma.rn.f32x2 %0, %1, %2, %3;" : "=l"(d) : "l"(a), "l"(b), "l"(c)); return d; }
__device__ __forceinline__ u64 add2(u64 a, u64 b){ u64 d; asm("add.rn.f32x2 %0, %1, %2;" : "=l"(d) : "l"(a), "l"(b)); return d; }
__device__ __forceinline__ void upk(u64 v, float& lo, float& hi){ asm("mov.b64 {%0, %1}, %2;" : "=f"(lo), "=f"(hi) : "l"(v)); }
__device__ __forceinline__ u64 pkf2(float lo, float hi){ u64 r; asm("mov.b64 %0, {%1, %2};" : "=l"(r) : "f"(lo), "f"(hi)); return r; }
__device__ __forceinline__ unsigned cvt_h2(float a, float b){ unsigned r; asm("cvt.rn.f16x2.f32 %0, %1, %2;" : "=r"(r) : "f"(b), "f"(a)); return r; }
__device__ __forceinline__ unsigned hex2(unsigned x){ unsigned r; asm("ex2.approx.f16x2 %0, %1;" : "=r"(r) : "r"(x)); return r; }
__device__ __forceinline__ unsigned hadd2(unsigned a, unsigned b){ unsigned r; asm("add.rn.f16x2 %0, %1, %2;" : "=r"(r) : "r"(a), "r"(b)); return r; }

// ==== kernel 1: main pass (coefficient prep inlined, 268M exps) ====
// CTA = 128 i's  x  one 32-j chunk.
// smem: per (j, quad q) a 48B record: {A01,B01}{A23,B23}{G01,G23}
__global__ void __launch_bounds__(IB) btc_main(const float* __restrict__ z,
                                               const float* __restrict__ zm,
                                               const float* __restrict__ zl)
{
    __shared__ float sC[JC*NQ*12];   // 24KB

    const int ch    = blockIdx.y;
    const int jbase = ch * JC;
    const int i     = blockIdx.x * IB + threadIdx.x;

    if (blockIdx.x == 0 && blockIdx.y == 0 && threadIdx.x == 0) d_ctr = 0;

    // ---- inline coefficient prep for this chunk's 32 j x 64 l ----
    #pragma unroll
    for (int k = 0; k < (JC*LATENT)/IB; k++) {
        int idx = threadIdx.x + k*IB;          // 0..2047, coalesced LDG
        int j = idx >> 6, l = idx & 63;
        float m  = zm[(jbase + j)*LATENT + l];
        float lv = zl[(jbase + j)*LATENT + l];
        float invs = ex2f(-lv * LOG2E_F);      // exp(-lv)
        float a = -0.5f * invs;
        int q = l >> 2;
        int aoff = (l & 2) * 2 + (l & 1);      // 0,1,4,5
        float* rec = &sC[(j*NQ + q)*12];
        rec[aoff    ] = a * LOG2E_F;                              // A
        rec[aoff + 2] = invs * m * LOG2E_F;                       // B
        rec[8 + (l&3)] = (a*m*m - 0.5f*(lv + LOG2PI_F)) * LOG2E_F; // G
    }
    __syncthreads();

    // ---- z row in registers, packed f32x2 ----
    u64 zr[NP];
    const float4* zp4 = (const float4*)(z + i*LATENT);
    #pragma unroll
    for (int q = 0; q < LATENT/4; q++) {
        float4 v = zp4[q];
        zr[2*q  ] = pkf2(v.x, v.y);
        zr[2*q+1] = pkf2(v.z, v.w);
    }

    unsigned hacc[NP];
    #pragma unroll
    for (int p = 0; p < NP; p++) hacc[p] = 0u;

    float M = -1e30f, T = 0.f;

    for (int jl = 0; jl < JC; jl++) {
        const ulonglong2* r2 = (const ulonglong2*)&sC[jl*NQ*12];
        u64 s2 = 0ull;
        #pragma unroll
        for (int q = 0; q < NQ; q++) {
            ulonglong2 ab0 = r2[3*q    ];        // {A01, B01}
            ulonglong2 ab1 = r2[3*q + 1];        // {A23, B23}
            ulonglong2 gg  = r2[3*q + 2];        // {G01, G23}
            u64 t0 = fma2(ab0.x, zr[2*q  ], ab0.y);
            u64 p0 = fma2(t0,    zr[2*q  ], gg.x);
            u64 t1 = fma2(ab1.x, zr[2*q+1], ab1.y);
            u64 p1 = fma2(t1,    zr[2*q+1], gg.y);
            s2 = add2(s2, p0);
            s2 = add2(s2, p1);
            float a0, a1, b0, b1;
            upk(p0, a0, a1);
            upk(p1, b0, b1);
            hacc[2*q  ] = hadd2(hacc[2*q  ], hex2(cvt_h2(a0, a1)));
            hacc[2*q+1] = hadd2(hacc[2*q+1], hex2(cvt_h2(b0, b1)));
        }
        float s0, s1; upk(s2, s0, s1);
        float S  = s0 + s1;                       // S_ij in log2 domain
        float nM = fmaxf(M, S);
        T = T * ex2f(M - nM) + ex2f(S - nM);      // branchless online LSE
        M = nM;
    }

    // write partials (coalesced over i)
    #pragma unroll
    for (int p = 0; p < NP; p++)
        d_accP[(ch*NP + p)*BATCH + i] = hacc[p];
    d_m2P[ch*BATCH + i] = M;
    d_t2P[ch*BATCH + i] = T;
}

// ==== kernel 2: fused reduce + KL + final mean (last-block pattern) ====
// 128 CTAs x 256 threads. CTA owns 16 i's; 16 groups split pairs/chunks/KL.
__global__ void __launch_bounds__(256) btc_reduce(const float* __restrict__ zm,
                                                  const float* __restrict__ zl,
                                                  float* __restrict__ out)
{
    __shared__ float s_lqp[16][16];
    __shared__ float s_m  [16][16];
    __shared__ float s_t  [16][16];
    __shared__ float s_kl [16][16];
    __shared__ float sh[256];
    __shared__ unsigned s_done;

    const int li = threadIdx.x & 15;       // i within block
    const int g  = threadIdx.x >> 4;       // group 0..15
    const int i  = blockIdx.x * 16 + li;

    // Phase A: per-dim sums across 64 chunks -> log2 (2 pairs per group)
    float lqp = 0.f;
    #pragma unroll
    for (int pp = 0; pp < 2; pp++) {
        const int p = g + pp*16;
        float s0 = 0.f, s1 = 0.f;
        #pragma unroll 16
        for (int chn = 0; chn < NJ; chn++) {
            __half2 h = *reinterpret_cast<const __half2*>(&d_accP[(chn*NP + p)*BATCH + i]);
            float2 f = __half22float2(h);
            s0 += f.x; s1 += f.y;
        }
        lqp += lg2f(s0) + lg2f(s1);
    }
    s_lqp[g][li] = lqp;

    // KL terms: 4 l's per group
    {
        float kl = 0.f;
        #pragma unroll
        for (int c = 0; c < 4; c++) {
            int l = g*4 + c;
            float m  = zm[i*LATENT + l];
            float lv = zl[i*LATENT + l];
            kl += m*m + ex2f(lv * LOG2E_F) - lv - 1.f;
        }
        s_kl[g][li] = kl;
    }

    // Phase B: chunk-LSE combine, 4 chunks per group
    float M = -1e30f, T = 0.f;
    #pragma unroll
    for (int cc = 0; cc < 4; cc++) {
        const int chn = g*4 + cc;
        float m = d_m2P[chn*BATCH + i];
        float t = d_t2P[chn*BATCH + i];
        float nM = fmaxf(M, m);
        T = T * ex2f(M - nM) + t * ex2f(m - nM);
        M = nM;
    }
    s_m[g][li] = M;
    s_t[g][li] = T;
    __syncthreads();

    if (threadIdx.x < 16) {
        const int ii = blockIdx.x * 16 + threadIdx.x;
        float lqp_tot = 0.f, kl_tot = 0.f;
        float Mf = -1e30f, Tf = 0.f;
        #pragma unroll
        for (int gg = 0; gg < 16; gg++) {
            lqp_tot += s_lqp[gg][threadIdx.x];
            kl_tot  += s_kl [gg][threadIdx.x];
            float m = s_m[gg][threadIdx.x], t = s_t[gg][threadIdx.x];
            float nM = fmaxf(Mf, m);
            Tf = Tf * ex2f(Mf - nM) + t * ex2f(m - nM);
            Mf = nM;
        }
        float lq2 = Mf + lg2f(Tf);
        d_val[ii] = 5.0f * LN2_F * (lq2 - lqp_tot) + 0.5f * kl_tot;
    }
    __syncthreads();

    // last CTA computes the deterministic mean
    __threadfence();
    if (threadIdx.x == 0) s_done = atomicAdd(&d_ctr, 1);
    __syncthreads();
    if (s_done == (BATCH/16) - 1) {
        __threadfence();
        float s = 0.f;
        for (int k = threadIdx.x; k < BATCH; k += 256) s += d_val[k];
        sh[threadIdx.x] = s;
        __syncthreads();
        for (int st = 128; st > 0; st >>= 1) {
            if (threadIdx.x < st) sh[threadIdx.x] += sh[threadIdx.x + st];
            __syncthreads();
        }
        if (threadIdx.x == 0) out[0] = sh[0] / (float)BATCH;
    }
}

extern "C" void kernel_launch(void* const* d_in, const int* in_sizes, int n_in,
                              void* d_out, int out_size)
{
    const float* z  = (const float*)d_in[0];
    const float* zm = (const float*)d_in[1];
    const float* zl = (const float*)d_in[2];
    (void)in_sizes; (void)n_in; (void)out_size;

    btc_main<<<dim3(BATCH/IB, NJ), IB>>>(z, zm, zl);
    btc_reduce<<<BATCH/16, 256>>>(zm, zl, (float*)d_out);
}